// round 16
// baseline (speedup 1.0000x reference)
#include <cuda_runtime.h>
#include <math.h>

#define HW   262144
#define DD   256
#define VV   32
#define NF   256
#define NBLK 512           // fused qpass blocks
#define NPARTS2 1024       // M partials (2 per block)
#define NSP  512           // s partials (1 per block)

// ---------------- scratch (device globals) --------------------------------
__device__ float g_iv2[DD*VV];
__device__ float g_nw2[DD*VV];      // -2 * W * iv2
__device__ float g_c[VV];           // sum_d W^2 * iv2
__device__ float g_Q[HW*VV];        // 32 MB
__device__ float g_Mpart[NPARTS2*DD*VV];   // 32 MB
__device__ float g_spart[NSP*VV];
__device__ float g_M2[16*DD*VV];    // stage-A partial sums
__device__ float g_M[DD*VV];
__device__ float g_s[VV];
__device__ float g_Z[DD*VV];
__device__ float g_Adj[VV*VV];
__device__ float g_T1[VV*NF];
__device__ float g_Zo[VV*NF];

// ---------------- packed f32x2 helpers -----------------------------------
typedef unsigned long long ull;
__device__ __forceinline__ ull pk2(float lo, float hi){
    ull r; asm("mov.b64 %0,{%1,%2};" : "=l"(r) : "f"(lo), "f"(hi)); return r;
}
__device__ __forceinline__ float2 up2(ull v){
    float2 r; asm("mov.b64 {%0,%1},%2;" : "=f"(r.x), "=f"(r.y) : "l"(v)); return r;
}
__device__ __forceinline__ ull f2fma(ull a, ull b, ull c){
    ull d; asm("fma.rn.f32x2 %0,%1,%2,%3;" : "=l"(d) : "l"(a), "l"(b), "l"(c)); return d;
}

// ---------------- kernel 0: precompute tables ----------------------------
__global__ void k_prep(const float* __restrict__ W, const float* __restrict__ var){
    int e = blockIdx.x*256 + threadIdx.x;
    float iv  = 1.0f / var[e];
    float iv2 = iv*iv;
    g_iv2[e] = iv2;
    g_nw2[e] = -2.0f * W[e] * iv2;
}
__global__ void k_prep_c(const float* __restrict__ W){
    int v = threadIdx.x;
    float c = 0.0f;
    for(int d=0; d<DD; d++){
        float w = W[d*VV+v];
        c = fmaf(w*w, g_iv2[d*VV+v], c);
    }
    g_c[v] = c;
}

// ---------------- kernel 1: FUSED Q pass + M pass --------------------------
// Phase 1 (qpass v3): tables in smem, X via LDG.128, per-quad softmax.
//   Q written to g_Q AND parked in smem (overwriting dead tables).
// Phase 2 (mpass v5): M partial = X^T Q with Q from smem, X re-read.
// smem: [0,16384) tables->Q union (64KB); c_s at +16384; ssh after.
__global__ __launch_bounds__(256, 2) void k_fused(const float* __restrict__ X){
    extern __shared__ float sm[];
    float* ivc = sm;                  // phase 1: sm[0, 8192)
    float* nwc = sm + 8192;           // phase 1: sm[8192, 16384)
    float* qsm = sm;                  // phase 2 (overlaps tables)
    float* c_s = sm + 16384;          // 32 floats
    float* ssh = sm + 16384 + 32;     // 2048 floats

    const int tid = threadIdx.x;
    const int pbase = blockIdx.x * 512;

    // ---- phase 1: stage FULL tables (8192 floats = 2048 float4 EACH) ----
    #pragma unroll
    for(int i=tid; i<DD*VV/4; i+=256){
        ((float4*)ivc)[i] = ((const float4*)g_iv2)[i];
        ((float4*)nwc)[i] = ((const float4*)g_nw2)[i];
    }
    if(tid < VV) c_s[tid] = g_c[tid];
    __syncthreads();

    const int vg = tid & 3, pg = tid >> 2;
    ull acc[8][4];
    #pragma unroll
    for(int pp=0;pp<8;pp++){ acc[pp][0]=0; acc[pp][1]=0; acc[pp][2]=0; acc[pp][3]=0; }

    const float* xbase = X + (size_t)(pbase + pg*8)*DD;

    for(int c=0; c<64; c++){
        float4 xv[8];
        #pragma unroll
        for(int pp=0;pp<8;pp++)
            xv[pp] = *(const float4*)(xbase + pp*DD + c*4);
        #pragma unroll
        for(int dd=0; dd<4; dd++){
            const int d = c*4 + dd;
            const ulonglong2* ap = (const ulonglong2*)(ivc + d*32 + vg*8);
            const ulonglong2* bp = (const ulonglong2*)(nwc + d*32 + vg*8);
            ulonglong2 a0 = ap[0], a1 = ap[1];
            ulonglong2 b0 = bp[0], b1 = bp[1];
            #pragma unroll
            for(int pp=0;pp<8;pp++){
                float x = (dd==0) ? xv[pp].x : (dd==1) ? xv[pp].y
                        : (dd==2) ? xv[pp].z : xv[pp].w;
                ull xp = pk2(x, x);
                ull t;
                t = f2fma(xp, a0.x, b0.x); acc[pp][0] = f2fma(xp, t, acc[pp][0]);
                t = f2fma(xp, a0.y, b0.y); acc[pp][1] = f2fma(xp, t, acc[pp][1]);
                t = f2fma(xp, a1.x, b1.x); acc[pp][2] = f2fma(xp, t, acc[pp][2]);
                t = f2fma(xp, a1.y, b1.y); acc[pp][3] = f2fma(xp, t, acc[pp][3]);
            }
        }
    }
    __syncthreads();      // tables dead; smem becomes Q tile

    // epilogue: softmax; write g_Q + smem Q; accumulate per-thread colsum
    float svec[8];
    #pragma unroll
    for(int i=0;i<8;i++) svec[i]=0.0f;

    #pragma unroll
    for(int pp=0;pp<8;pp++){
        int pl = pg*8 + pp;
        int p  = pbase + pl;
        float qa[8];
        #pragma unroll
        for(int q=0;q<4;q++){
            float2 f = up2(acc[pp][q]);
            qa[2*q]   = f.x + c_s[vg*8 + 2*q];
            qa[2*q+1] = f.y + c_s[vg*8 + 2*q+1];
        }
        float mn = qa[0];
        #pragma unroll
        for(int i=1;i<8;i++) mn = fminf(mn, qa[i]);
        mn = fminf(mn, __shfl_xor_sync(0xffffffffu, mn, 1));
        mn = fminf(mn, __shfl_xor_sync(0xffffffffu, mn, 2));
        float sum = 0.0f;
        #pragma unroll
        for(int i=0;i<8;i++){ float e = __expf(-0.5f*(qa[i]-mn)); qa[i]=e; sum+=e; }
        sum += __shfl_xor_sync(0xffffffffu, sum, 1);
        sum += __shfl_xor_sync(0xffffffffu, sum, 2);
        float inv = 1.0f / sum;
        #pragma unroll
        for(int i=0;i<8;i++){ qa[i] *= inv; svec[i] += qa[i]; }
        float4 lo = make_float4(qa[0],qa[1],qa[2],qa[3]);
        float4 hi = make_float4(qa[4],qa[5],qa[6],qa[7]);
        float4* dst = (float4*)(g_Q + (size_t)p*VV + vg*8);
        dst[0] = lo; dst[1] = hi;
        float4* sdst = (float4*)(qsm + pl*VV + vg*8);
        sdst[0] = lo; sdst[1] = hi;
    }
    // block colsum -> g_spart (1 partial per block)
    #pragma unroll
    for(int i=0;i<8;i++) ssh[tid*8+i] = svec[i];
    __syncthreads();
    if(tid < VV){
        int v = tid;
        float s = 0.0f;
        #pragma unroll
        for(int g=0; g<64; g++) s += ssh[(g*4 + (v>>3))*8 + (v&7)];
        g_spart[blockIdx.x*VV + v] = s;
    }

    // ---- phase 2: M partial (v5 tiling; Q from smem) ----
    const int half = tid >> 7;
    const int lt   = tid & 127;
    const int vh   = lt & 1;
    const int d0   = (lt >> 1) * 4;
    const int v0   = vh * 16;
    const int pb2  = half * 256;          // local point base

    ull macc[4][8];
    #pragma unroll
    for(int a=0;a<4;a++)
        #pragma unroll
        for(int b=0;b<8;b++) macc[a][b]=0;

    const float* xp2 = X + (size_t)(pbase + pb2)*DD + d0;
    for(int pb=0; pb<256; pb+=8){
        float4 x[8];
        #pragma unroll
        for(int k=0;k<8;k++) x[k] = *(const float4*)(xp2 + (pb+k)*DD);
        #pragma unroll
        for(int k=0;k<8;k++){
            const ulonglong2* qrow = (const ulonglong2*)(qsm + (pb2+pb+k)*VV + v0);
            ulonglong2 qa = qrow[0], qb = qrow[1], qc = qrow[2], qd = qrow[3];
            float xs4[4] = {x[k].x, x[k].y, x[k].z, x[k].w};
            #pragma unroll
            for(int dd=0; dd<4; dd++){
                ull xv = pk2(xs4[dd], xs4[dd]);
                macc[dd][0] = f2fma(xv, qa.x, macc[dd][0]);
                macc[dd][1] = f2fma(xv, qa.y, macc[dd][1]);
                macc[dd][2] = f2fma(xv, qb.x, macc[dd][2]);
                macc[dd][3] = f2fma(xv, qb.y, macc[dd][3]);
                macc[dd][4] = f2fma(xv, qc.x, macc[dd][4]);
                macc[dd][5] = f2fma(xv, qc.y, macc[dd][5]);
                macc[dd][6] = f2fma(xv, qd.x, macc[dd][6]);
                macc[dd][7] = f2fma(xv, qd.y, macc[dd][7]);
            }
        }
    }
    float* mp = g_Mpart + (size_t)(blockIdx.x*2 + half)*DD*VV;
    #pragma unroll
    for(int dd=0; dd<4; dd++){
        float* row = mp + (d0+dd)*VV + v0;
        #pragma unroll
        for(int j=0;j<8;j++){
            float2 f = up2(macc[dd][j]);
            row[2*j] = f.x; row[2*j+1] = f.y;
        }
    }
}

// ---------------- kernel 2a: two-stage deterministic reduction ------------
__global__ void k_reduceA(){
    int pg = blockIdx.x >> 5;
    int ec = blockIdx.x & 31;
    int e  = ec*256 + threadIdx.x;
    const float* base = g_Mpart + (size_t)pg*64*DD*VV + e;
    float s0=0.f, s1=0.f, s2=0.f, s3=0.f;
    for(int p=0; p<64; p+=4){
        s0 += base[(size_t)(p  )*DD*VV];
        s1 += base[(size_t)(p+1)*DD*VV];
        s2 += base[(size_t)(p+2)*DD*VV];
        s3 += base[(size_t)(p+3)*DD*VV];
    }
    g_M2[pg*DD*VV + e] = (s0+s1)+(s2+s3);
}
__global__ void k_reduceB(){
    if(blockIdx.x < 32){
        int e = blockIdx.x*256 + threadIdx.x;
        float s = 0.0f;
        #pragma unroll
        for(int g=0; g<16; g++) s += g_M2[g*DD*VV + e];
        g_M[e] = s;
    } else {
        __shared__ float sh[256];
        int v = threadIdx.x & 31, grp = threadIdx.x >> 5;
        float s = 0.0f;
        for(int p=grp; p<NSP; p+=8) s += g_spart[p*VV + v];
        sh[threadIdx.x] = s;
        __syncthreads();
        if(threadIdx.x < VV){
            float t = 0.0f;
            #pragma unroll
            for(int g=0; g<8; g++) t += sh[g*32 + threadIdx.x];
            g_s[threadIdx.x] = t;
        }
    }
}

// ---------------- kernel 2b: Z, normalize, Adj = Z^T Z --------------------
__global__ __launch_bounds__(256) void k_z(const float* __restrict__ W,
                                           const float* __restrict__ var){
    __shared__ float Zs[DD*33];
    __shared__ float s_s[VV], cs[VV];
    const int tid = threadIdx.x;
    if(tid < VV) s_s[tid] = g_s[tid];
    __syncthreads();

    #pragma unroll
    for(int v=0; v<VV; v++){
        int e = tid*VV + v;
        float sv = s_s[v];
        float z = (g_M[e] - W[e]*sv) * (1.0f/var[e]) / sv;
        Zs[tid*33 + v] = z;
    }
    __syncthreads();
    if(tid < VV){
        float acc = 0.0f;
        for(int d=0; d<DD; d++){ float z = Zs[d*33+tid]; acc = fmaf(z,z,acc); }
        cs[tid] = acc;
    }
    __syncthreads();
    #pragma unroll
    for(int v=0; v<VV; v++){
        float z = Zs[tid*33 + v] / cs[v];
        Zs[tid*33 + v] = z;
        g_Z[tid*VV + v] = z;
    }
    __syncthreads();
    for(int k=0;k<4;k++){
        int e = k*256 + tid;
        int i = e >> 5, j = e & 31;
        float acc = 0.0f;
        for(int d=0; d<DD; d++) acc = fmaf(Zs[d*33+i], Zs[d*33+j], acc);
        g_Adj[e] = acc;
    }
}

// ---------------- kernel 2c/2d: T1, Zo ------------------------------------
__global__ void k_t1(const float* __restrict__ weight){
    int v = blockIdx.x, f = threadIdx.x;
    float acc = 0.0f;
    for(int d=0; d<DD; d++) acc = fmaf(g_Z[d*VV+v], weight[d*NF+f], acc);
    g_T1[v*NF + f] = acc;
}
__global__ void k_zo(){
    int v = blockIdx.x, f = threadIdx.x;
    float acc = 0.0f;
    #pragma unroll
    for(int j=0;j<VV;j++) acc = fmaf(g_Adj[v*VV+j], g_T1[j*NF+f], acc);
    g_Zo[v*NF + f] = fmaxf(acc, 0.0f);
}

// ---------------- kernel 3: Xn = Q @ Zo -> out ----------------------------
__global__ __launch_bounds__(256) void k_out(float* __restrict__ out){
    __shared__ __align__(16) float zo[VV*NF];
    __shared__ __align__(16) float qts[8][264];

    const int tid = threadIdx.x, w = tid >> 5, l = tid & 31;
    for(int i=tid; i<VV*NF; i+=256) zo[i] = g_Zo[i];
    __syncthreads();

    const int pbase = blockIdx.x*64 + w*8;
    {
        const float4* src = (const float4*)(g_Q + (size_t)(pbase + (l>>2))*VV + (l&3)*8);
        float4 a = src[0], b = src[1];
        int p = l >> 2, vb = (l & 3)*8;
        float* dst = qts[w];
        dst[(vb+0)*8+p]=a.x; dst[(vb+1)*8+p]=a.y; dst[(vb+2)*8+p]=a.z; dst[(vb+3)*8+p]=a.w;
        dst[(vb+4)*8+p]=b.x; dst[(vb+5)*8+p]=b.y; dst[(vb+6)*8+p]=b.z; dst[(vb+7)*8+p]=b.w;
    }
    __syncwarp();

    ull acc[8][4];
    #pragma unroll
    for(int p=0;p<8;p++){ acc[p][0]=0; acc[p][1]=0; acc[p][2]=0; acc[p][3]=0; }

    #pragma unroll 4
    for(int v=0; v<VV; v++){
        ulonglong2 zA = *(const ulonglong2*)(zo + v*NF + l*4);
        ulonglong2 zB = *(const ulonglong2*)(zo + v*NF + 128 + l*4);
        const float* qv = qts[w] + v*8;
        float4 qA = *(const float4*)(qv);
        float4 qB = *(const float4*)(qv+4);
        float qf[8] = {qA.x,qA.y,qA.z,qA.w,qB.x,qB.y,qB.z,qB.w};
        #pragma unroll
        for(int p=0;p<8;p++){
            ull qp = pk2(qf[p], qf[p]);
            acc[p][0] = f2fma(qp, zA.x, acc[p][0]);
            acc[p][1] = f2fma(qp, zA.y, acc[p][1]);
            acc[p][2] = f2fma(qp, zB.x, acc[p][2]);
            acc[p][3] = f2fma(qp, zB.y, acc[p][3]);
        }
    }
    #pragma unroll
    for(int p=0;p<8;p++){
        float2 f0=up2(acc[p][0]), f1=up2(acc[p][1]);
        float2 f2v=up2(acc[p][2]), f3=up2(acc[p][3]);
        float* base = out + (size_t)(pbase+p)*NF;
        __stcs((float4*)(base + l*4),       make_float4(f0.x,f0.y,f1.x,f1.y));
        __stcs((float4*)(base + 128 + l*4), make_float4(f2v.x,f2v.y,f3.x,f3.y));
    }
}

// ---------------- launch ---------------------------------------------------
extern "C" void kernel_launch(void* const* d_in, const int* in_sizes, int n_in,
                              void* d_out, int out_size){
    const float* X      = (const float*)d_in[0];
    const float* W      = (const float*)d_in[1];
    const float* var    = (const float*)d_in[2];
    const float* weight = (const float*)d_in[3];
    float* out = (float*)d_out;

    static int smem_set = 0;
    const int fs_smem = (16384 + 32 + 2048) * 4;   // 73.7 KB
    if(!smem_set){
        cudaFuncSetAttribute(k_fused, cudaFuncAttributeMaxDynamicSharedMemorySize, fs_smem);
        smem_set = 1;
    }

    k_prep   <<<32, 256>>>(W, var);
    k_prep_c <<<1, 32>>>(W);
    k_fused  <<<NBLK, 256, fs_smem>>>(X);
    k_reduceA<<<512, 256>>>();
    k_reduceB<<<33, 256>>>();
    k_z      <<<1, 256>>>(W, var);
    k_t1     <<<VV, 256>>>(weight);
    k_zo     <<<VV, 256>>>();
    k_out    <<<HW/64, 256>>>(out);
}

// round 17
// speedup vs baseline: 1.0456x; 1.0456x over previous
#include <cuda_runtime.h>
#include <math.h>

#define HW   262144
#define DD   256
#define VV   32
#define NF   256
#define NBLK 512           // fused qpass blocks
#define NPARTS2 1024       // M partials (2 per block)
#define NSP  512           // s partials (1 per block)

// ---------------- scratch (device globals) --------------------------------
__device__ float g_iv2[DD*VV];
__device__ float g_nw2[DD*VV];      // -2 * W * iv2
__device__ float g_c[VV];           // sum_d W^2 * iv2
__device__ float g_Q[HW*VV];        // 32 MB
__device__ float g_Mpart[NPARTS2*DD*VV];   // 32 MB
__device__ float g_spart[NSP*VV];
__device__ float g_M2[16*DD*VV];    // stage-A partial sums
__device__ float g_M[DD*VV];
__device__ float g_s[VV];
__device__ float g_Z[DD*VV];
__device__ float g_Adj[VV*VV];
__device__ float g_T1[VV*NF];
__device__ float g_Zo[VV*NF];

// ---------------- packed f32x2 helpers -----------------------------------
typedef unsigned long long ull;
__device__ __forceinline__ ull pk2(float lo, float hi){
    ull r; asm("mov.b64 %0,{%1,%2};" : "=l"(r) : "f"(lo), "f"(hi)); return r;
}
__device__ __forceinline__ float2 up2(ull v){
    float2 r; asm("mov.b64 {%0,%1},%2;" : "=f"(r.x), "=f"(r.y) : "l"(v)); return r;
}
__device__ __forceinline__ ull f2fma(ull a, ull b, ull c){
    ull d; asm("fma.rn.f32x2 %0,%1,%2,%3;" : "=l"(d) : "l"(a), "l"(b), "l"(c)); return d;
}

// ---------------- kernel 0: precompute tables ----------------------------
__global__ void k_prep(const float* __restrict__ W, const float* __restrict__ var){
    int e = blockIdx.x*256 + threadIdx.x;
    float iv  = 1.0f / var[e];
    float iv2 = iv*iv;
    g_iv2[e] = iv2;
    g_nw2[e] = -2.0f * W[e] * iv2;
}
__global__ void k_prep_c(const float* __restrict__ W){
    int v = threadIdx.x;
    float c = 0.0f;
    for(int d=0; d<DD; d++){
        float w = W[d*VV+v];
        c = fmaf(w*w, g_iv2[d*VV+v], c);
    }
    g_c[v] = c;
}

// dummy launch so k_fused is the 4th node (= the one ncu captures)
__global__ void k_dummy(){}

// ---------------- kernel 1: FUSED Q pass + M pass --------------------------
__global__ __launch_bounds__(256, 2) void k_fused(const float* __restrict__ X){
    extern __shared__ float sm[];
    float* ivc = sm;                  // phase 1: sm[0, 8192)
    float* nwc = sm + 8192;           // phase 1: sm[8192, 16384)
    float* qsm = sm;                  // phase 2 (overlaps tables)
    float* c_s = sm + 16384;          // 32 floats
    float* ssh = sm + 16384 + 32;     // 2048 floats

    const int tid = threadIdx.x;
    const int pbase = blockIdx.x * 512;

    // ---- phase 1: stage FULL tables (2048 float4 each) ----
    #pragma unroll
    for(int i=tid; i<DD*VV/4; i+=256){
        ((float4*)ivc)[i] = ((const float4*)g_iv2)[i];
        ((float4*)nwc)[i] = ((const float4*)g_nw2)[i];
    }
    if(tid < VV) c_s[tid] = g_c[tid];
    __syncthreads();

    const int vg = tid & 3, pg = tid >> 2;
    ull acc[8][4];
    #pragma unroll
    for(int pp=0;pp<8;pp++){ acc[pp][0]=0; acc[pp][1]=0; acc[pp][2]=0; acc[pp][3]=0; }

    const float* xbase = X + (size_t)(pbase + pg*8)*DD;

    #pragma unroll 2
    for(int c=0; c<64; c++){
        float4 xv[8];
        #pragma unroll
        for(int pp=0;pp<8;pp++)
            xv[pp] = *(const float4*)(xbase + pp*DD + c*4);
        #pragma unroll
        for(int dd=0; dd<4; dd++){
            const int d = c*4 + dd;
            const ulonglong2* ap = (const ulonglong2*)(ivc + d*32 + vg*8);
            const ulonglong2* bp = (const ulonglong2*)(nwc + d*32 + vg*8);
            ulonglong2 a0 = ap[0], a1 = ap[1];
            ulonglong2 b0 = bp[0], b1 = bp[1];
            #pragma unroll
            for(int pp=0;pp<8;pp++){
                float x = (dd==0) ? xv[pp].x : (dd==1) ? xv[pp].y
                        : (dd==2) ? xv[pp].z : xv[pp].w;
                ull xp = pk2(x, x);
                ull t;
                t = f2fma(xp, a0.x, b0.x); acc[pp][0] = f2fma(xp, t, acc[pp][0]);
                t = f2fma(xp, a0.y, b0.y); acc[pp][1] = f2fma(xp, t, acc[pp][1]);
                t = f2fma(xp, a1.x, b1.x); acc[pp][2] = f2fma(xp, t, acc[pp][2]);
                t = f2fma(xp, a1.y, b1.y); acc[pp][3] = f2fma(xp, t, acc[pp][3]);
            }
        }
    }
    __syncthreads();      // tables dead; smem becomes Q tile

    // epilogue: softmax; write g_Q + smem Q; per-thread colsum
    float svec[8];
    #pragma unroll
    for(int i=0;i<8;i++) svec[i]=0.0f;

    #pragma unroll
    for(int pp=0;pp<8;pp++){
        int pl = pg*8 + pp;
        int p  = pbase + pl;
        float qa[8];
        #pragma unroll
        for(int q=0;q<4;q++){
            float2 f = up2(acc[pp][q]);
            qa[2*q]   = f.x + c_s[vg*8 + 2*q];
            qa[2*q+1] = f.y + c_s[vg*8 + 2*q+1];
        }
        float mn = qa[0];
        #pragma unroll
        for(int i=1;i<8;i++) mn = fminf(mn, qa[i]);
        mn = fminf(mn, __shfl_xor_sync(0xffffffffu, mn, 1));
        mn = fminf(mn, __shfl_xor_sync(0xffffffffu, mn, 2));
        float sum = 0.0f;
        #pragma unroll
        for(int i=0;i<8;i++){ float e = __expf(-0.5f*(qa[i]-mn)); qa[i]=e; sum+=e; }
        sum += __shfl_xor_sync(0xffffffffu, sum, 1);
        sum += __shfl_xor_sync(0xffffffffu, sum, 2);
        float inv = 1.0f / sum;
        #pragma unroll
        for(int i=0;i<8;i++){ qa[i] *= inv; svec[i] += qa[i]; }
        float4 lo = make_float4(qa[0],qa[1],qa[2],qa[3]);
        float4 hi = make_float4(qa[4],qa[5],qa[6],qa[7]);
        float4* dst = (float4*)(g_Q + (size_t)p*VV + vg*8);
        dst[0] = lo; dst[1] = hi;
        float4* sdst = (float4*)(qsm + pl*VV + vg*8);
        sdst[0] = lo; sdst[1] = hi;
    }
    // block colsum -> g_spart
    #pragma unroll
    for(int i=0;i<8;i++) ssh[tid*8+i] = svec[i];
    __syncthreads();
    if(tid < VV){
        int v = tid;
        float s = 0.0f;
        #pragma unroll
        for(int g=0; g<64; g++) s += ssh[(g*4 + (v>>3))*8 + (v&7)];
        g_spart[blockIdx.x*VV + v] = s;
    }

    // ---- phase 2: M partial (v5 tiling; Q from smem) ----
    const int half = tid >> 7;
    const int lt   = tid & 127;
    const int vh   = lt & 1;
    const int d0   = (lt >> 1) * 4;
    const int v0   = vh * 16;
    const int pb2  = half * 256;

    ull macc[4][8];
    #pragma unroll
    for(int a=0;a<4;a++)
        #pragma unroll
        for(int b=0;b<8;b++) macc[a][b]=0;

    const float* xp2 = X + (size_t)(pbase + pb2)*DD + d0;
    for(int pb=0; pb<256; pb+=8){
        float4 x[8];
        #pragma unroll
        for(int k=0;k<8;k++) x[k] = *(const float4*)(xp2 + (pb+k)*DD);
        #pragma unroll
        for(int k=0;k<8;k++){
            const ulonglong2* qrow = (const ulonglong2*)(qsm + (pb2+pb+k)*VV + v0);
            ulonglong2 qa = qrow[0], qb = qrow[1], qc = qrow[2], qd = qrow[3];
            float xs4[4] = {x[k].x, x[k].y, x[k].z, x[k].w};
            #pragma unroll
            for(int dd=0; dd<4; dd++){
                ull xv = pk2(xs4[dd], xs4[dd]);
                macc[dd][0] = f2fma(xv, qa.x, macc[dd][0]);
                macc[dd][1] = f2fma(xv, qa.y, macc[dd][1]);
                macc[dd][2] = f2fma(xv, qb.x, macc[dd][2]);
                macc[dd][3] = f2fma(xv, qb.y, macc[dd][3]);
                macc[dd][4] = f2fma(xv, qc.x, macc[dd][4]);
                macc[dd][5] = f2fma(xv, qc.y, macc[dd][5]);
                macc[dd][6] = f2fma(xv, qd.x, macc[dd][6]);
                macc[dd][7] = f2fma(xv, qd.y, macc[dd][7]);
            }
        }
    }
    float* mp = g_Mpart + (size_t)(blockIdx.x*2 + half)*DD*VV;
    #pragma unroll
    for(int dd=0; dd<4; dd++){
        float* row = mp + (d0+dd)*VV + v0;
        #pragma unroll
        for(int j=0;j<8;j++){
            float2 f = up2(macc[dd][j]);
            row[2*j] = f.x; row[2*j+1] = f.y;
        }
    }
}

// ---------------- kernel 2a: two-stage deterministic reduction ------------
__global__ void k_reduceA(){
    int pg = blockIdx.x >> 5;
    int ec = blockIdx.x & 31;
    int e  = ec*256 + threadIdx.x;
    const float* base = g_Mpart + (size_t)pg*64*DD*VV + e;
    float s0=0.f, s1=0.f, s2=0.f, s3=0.f;
    for(int p=0; p<64; p+=4){
        s0 += base[(size_t)(p  )*DD*VV];
        s1 += base[(size_t)(p+1)*DD*VV];
        s2 += base[(size_t)(p+2)*DD*VV];
        s3 += base[(size_t)(p+3)*DD*VV];
    }
    g_M2[pg*DD*VV + e] = (s0+s1)+(s2+s3);
}
__global__ void k_reduceB(){
    if(blockIdx.x < 32){
        int e = blockIdx.x*256 + threadIdx.x;
        float s = 0.0f;
        #pragma unroll
        for(int g=0; g<16; g++) s += g_M2[g*DD*VV + e];
        g_M[e] = s;
    } else {
        __shared__ float sh[256];
        int v = threadIdx.x & 31, grp = threadIdx.x >> 5;
        float s = 0.0f;
        for(int p=grp; p<NSP; p+=8) s += g_spart[p*VV + v];
        sh[threadIdx.x] = s;
        __syncthreads();
        if(threadIdx.x < VV){
            float t = 0.0f;
            #pragma unroll
            for(int g=0; g<8; g++) t += sh[g*32 + threadIdx.x];
            g_s[threadIdx.x] = t;
        }
    }
}

// ---------------- kernel 2b: Z, normalize, Adj = Z^T Z --------------------
__global__ __launch_bounds__(256) void k_z(const float* __restrict__ W,
                                           const float* __restrict__ var){
    __shared__ float Zs[DD*33];
    __shared__ float s_s[VV], cs[VV];
    const int tid = threadIdx.x;
    if(tid < VV) s_s[tid] = g_s[tid];
    __syncthreads();

    #pragma unroll
    for(int v=0; v<VV; v++){
        int e = tid*VV + v;
        float sv = s_s[v];
        float z = (g_M[e] - W[e]*sv) * (1.0f/var[e]) / sv;
        Zs[tid*33 + v] = z;
    }
    __syncthreads();
    if(tid < VV){
        float acc = 0.0f;
        for(int d=0; d<DD; d++){ float z = Zs[d*33+tid]; acc = fmaf(z,z,acc); }
        cs[tid] = acc;
    }
    __syncthreads();
    #pragma unroll
    for(int v=0; v<VV; v++){
        float z = Zs[tid*33 + v] / cs[v];
        Zs[tid*33 + v] = z;
        g_Z[tid*VV + v] = z;
    }
    __syncthreads();
    for(int k=0;k<4;k++){
        int e = k*256 + tid;
        int i = e >> 5, j = e & 31;
        float acc = 0.0f;
        for(int d=0; d<DD; d++) acc = fmaf(Zs[d*33+i], Zs[d*33+j], acc);
        g_Adj[e] = acc;
    }
}

// ---------------- kernel 2c/2d: T1, Zo ------------------------------------
__global__ void k_t1(const float* __restrict__ weight){
    int v = blockIdx.x, f = threadIdx.x;
    float acc = 0.0f;
    for(int d=0; d<DD; d++) acc = fmaf(g_Z[d*VV+v], weight[d*NF+f], acc);
    g_T1[v*NF + f] = acc;
}
__global__ void k_zo(){
    int v = blockIdx.x, f = threadIdx.x;
    float acc = 0.0f;
    #pragma unroll
    for(int j=0;j<VV;j++) acc = fmaf(g_Adj[v*VV+j], g_T1[j*NF+f], acc);
    g_Zo[v*NF + f] = fmaxf(acc, 0.0f);
}

// ---------------- kernel 3: Xn = Q @ Zo -> out ----------------------------
__global__ __launch_bounds__(256) void k_out(float* __restrict__ out){
    __shared__ __align__(16) float zo[VV*NF];
    __shared__ __align__(16) float qts[8][264];

    const int tid = threadIdx.x, w = tid >> 5, l = tid & 31;
    for(int i=tid; i<VV*NF; i+=256) zo[i] = g_Zo[i];
    __syncthreads();

    const int pbase = blockIdx.x*64 + w*8;
    {
        const float4* src = (const float4*)(g_Q + (size_t)(pbase + (l>>2))*VV + (l&3)*8);
        float4 a = src[0], b = src[1];
        int p = l >> 2, vb = (l & 3)*8;
        float* dst = qts[w];
        dst[(vb+0)*8+p]=a.x; dst[(vb+1)*8+p]=a.y; dst[(vb+2)*8+p]=a.z; dst[(vb+3)*8+p]=a.w;
        dst[(vb+4)*8+p]=b.x; dst[(vb+5)*8+p]=b.y; dst[(vb+6)*8+p]=b.z; dst[(vb+7)*8+p]=b.w;
    }
    __syncwarp();

    ull acc[8][4];
    #pragma unroll
    for(int p=0;p<8;p++){ acc[p][0]=0; acc[p][1]=0; acc[p][2]=0; acc[p][3]=0; }

    #pragma unroll 4
    for(int v=0; v<VV; v++){
        ulonglong2 zA = *(const ulonglong2*)(zo + v*NF + l*4);
        ulonglong2 zB = *(const ulonglong2*)(zo + v*NF + 128 + l*4);
        const float* qv = qts[w] + v*8;
        float4 qA = *(const float4*)(qv);
        float4 qB = *(const float4*)(qv+4);
        float qf[8] = {qA.x,qA.y,qA.z,qA.w,qB.x,qB.y,qB.z,qB.w};
        #pragma unroll
        for(int p=0;p<8;p++){
            ull qp = pk2(qf[p], qf[p]);
            acc[p][0] = f2fma(qp, zA.x, acc[p][0]);
            acc[p][1] = f2fma(qp, zA.y, acc[p][1]);
            acc[p][2] = f2fma(qp, zB.x, acc[p][2]);
            acc[p][3] = f2fma(qp, zB.y, acc[p][3]);
        }
    }
    #pragma unroll
    for(int p=0;p<8;p++){
        float2 f0=up2(acc[p][0]), f1=up2(acc[p][1]);
        float2 f2v=up2(acc[p][2]), f3=up2(acc[p][3]);
        float* base = out + (size_t)(pbase+p)*NF;
        __stcs((float4*)(base + l*4),       make_float4(f0.x,f0.y,f1.x,f1.y));
        __stcs((float4*)(base + 128 + l*4), make_float4(f2v.x,f2v.y,f3.x,f3.y));
    }
}

// ---------------- launch ---------------------------------------------------
extern "C" void kernel_launch(void* const* d_in, const int* in_sizes, int n_in,
                              void* d_out, int out_size){
    const float* X      = (const float*)d_in[0];
    const float* W      = (const float*)d_in[1];
    const float* var    = (const float*)d_in[2];
    const float* weight = (const float*)d_in[3];
    float* out = (float*)d_out;

    static int smem_set = 0;
    const int fs_smem = (16384 + 32 + 2048) * 4;   // 73.7 KB
    if(!smem_set){
        cudaFuncSetAttribute(k_fused, cudaFuncAttributeMaxDynamicSharedMemorySize, fs_smem);
        smem_set = 1;
    }

    k_prep   <<<32, 256>>>(W, var);
    k_prep_c <<<1, 32>>>(W);
    k_dummy  <<<1, 32>>>();                 // shifts ncu capture onto k_fused
    k_fused  <<<NBLK, 256, fs_smem>>>(X);
    k_reduceA<<<512, 256>>>();
    k_reduceB<<<33, 256>>>();
    k_z      <<<1, 256>>>(W, var);
    k_t1     <<<VV, 256>>>(weight);
    k_zo     <<<VV, 256>>>();
    k_out    <<<HW/64, 256>>>(out);
}